// round 1
// baseline (speedup 1.0000x reference)
#include <cuda_runtime.h>

#define NN   100000
#define EE   1600000
#define IND  128
#define OUTD 64
#define MDIM 16
#define GHD  64

// ---------------- static device scratch (no allocations allowed) ----------------
__device__ float g_gate[EE];
__device__ float g_deg[NN];                 // deg, then dinv in-place
__device__ int   g_cnt[NN];
__device__ int   g_rowptr[NN + 1];
__device__ int   g_cursor[NN];
__device__ int   g_col[EE];
__device__ float g_val[EE];
__device__ float g_xw[(size_t)NN * IND];    // 51.2 MB (L2-resident working set)
__device__ float g_xbuf[(size_t)NN * IND];  // node features between layers
__device__ int   g_partial[1024];
__device__ int   g_is64;

// ---------------- helpers ----------------
__device__ __forceinline__ void load_edge(const void* ei, int e, int E, int is64,
                                          int& s, int& d) {
    if (is64) {
        const long long* p = (const long long*)ei;
        s = (int)p[e];
        d = (int)p[E + e];
    } else {
        const int* p = (const int*)ei;
        s = p[e];
        d = p[E + e];
    }
}

__device__ __forceinline__ unsigned long long pack2(float lo, float hi) {
    unsigned long long r;
    asm("mov.b64 %0, {%1, %2};" : "=l"(r) : "r"(__float_as_uint(lo)), "r"(__float_as_uint(hi)));
    return r;
}
__device__ __forceinline__ void unpack2(unsigned long long v, float& lo, float& hi) {
    unsigned int a, b;
    asm("mov.b64 {%0, %1}, %2;" : "=r"(a), "=r"(b) : "l"(v));
    lo = __uint_as_float(a);
    hi = __uint_as_float(b);
}
__device__ __forceinline__ void fma2(unsigned long long& acc, unsigned long long a,
                                     unsigned long long b) {
    asm("fma.rn.f32x2 %0, %1, %2, %0;" : "+l"(acc) : "l"(a), "l"(b));
}

// ---------------- dtype detection ----------------
__global__ void detect_kernel(const int* ei) {
    if (threadIdx.x == 0) {
        int all0 = 1;
        for (int i = 1; i < 256; i += 2)
            if (ei[i] != 0) { all0 = 0; break; }
        g_is64 = all0;  // int64: odd words are high halves of values < 2^17 -> 0
    }
}

// ---------------- init ----------------
__global__ void init_kernel(int n) {
    int i = blockIdx.x * blockDim.x + threadIdx.x;
    if (i < n) {
        g_deg[i] = 1.0f;  // self-loop weight
        g_cnt[i] = 0;
    }
}

// ---------------- edge gate MLP (f32x2) + degree + histogram ----------------
__global__ __launch_bounds__(256) void gate_kernel(
    const void* __restrict__ ei, const float* __restrict__ motif,
    const float* __restrict__ w1, const float* __restrict__ b1,
    const float* __restrict__ w2, const float* __restrict__ b2, int E) {
    __shared__ __align__(16) float sW1[GHD * GHD];  // [k][j], 16 KB
    __shared__ float sw2[GHD];
    __shared__ float sb1[GHD];
    for (int i = threadIdx.x; i < GHD * GHD; i += blockDim.x) sW1[i] = w1[i];
    if (threadIdx.x < GHD) {
        sw2[threadIdx.x] = w2[threadIdx.x];
        sb1[threadIdx.x] = b1[threadIdx.x];
    }
    __syncthreads();

    int e = blockIdx.x * blockDim.x + threadIdx.x;
    if (e >= E) return;
    int is64 = g_is64;
    int s, d;
    load_edge(ei, e, E, is64, s, d);

    float mu[MDIM], mv[MDIM];
    const float4* m4 = (const float4*)motif;
#pragma unroll
    for (int i = 0; i < 4; i++) {
        float4 a = m4[s * 4 + i];
        mu[i * 4 + 0] = a.x; mu[i * 4 + 1] = a.y; mu[i * 4 + 2] = a.z; mu[i * 4 + 3] = a.w;
        float4 b = m4[d * 4 + i];
        mv[i * 4 + 0] = b.x; mv[i * 4 + 1] = b.y; mv[i * 4 + 2] = b.z; mv[i * 4 + 3] = b.w;
    }

    unsigned long long acc[GHD / 2];
#pragma unroll
    for (int j = 0; j < GHD / 2; j++) acc[j] = pack2(sb1[2 * j], sb1[2 * j + 1]);

    const unsigned long long* W2p = (const unsigned long long*)sW1;
    auto body = [&](int k, float f) {
        unsigned long long ff = pack2(f, f);
#pragma unroll
        for (int j = 0; j < GHD / 2; j++) fma2(acc[j], ff, W2p[k * (GHD / 2) + j]);
    };
#pragma unroll
    for (int k = 0; k < 16; k++) body(k, mu[k]);
#pragma unroll
    for (int k = 0; k < 16; k++) body(16 + k, mv[k]);
#pragma unroll
    for (int k = 0; k < 16; k++) body(32 + k, fabsf(mu[k] - mv[k]));
#pragma unroll
    for (int k = 0; k < 16; k++) body(48 + k, mu[k] * mv[k]);

    float g = b2[0];
#pragma unroll
    for (int j = 0; j < GHD / 2; j++) {
        float lo, hi;
        unpack2(acc[j], lo, hi);
        g += fmaxf(lo, 0.0f) * sw2[2 * j] + fmaxf(hi, 0.0f) * sw2[2 * j + 1];
    }
    float gate = 1.0f / (1.0f + __expf(-g));
    g_gate[e] = gate;
    atomicAdd(&g_deg[d], gate);
    atomicAdd(&g_cnt[d], 1);
}

// ---------------- dinv ----------------
__global__ void dinv_kernel(int n) {
    int i = blockIdx.x * blockDim.x + threadIdx.x;
    if (i < n) g_deg[i] = rsqrtf(g_deg[i]);  // deg >= 1 always
}

// ---------------- 3-phase exclusive scan of g_cnt -> g_rowptr / g_cursor ----------------
__global__ void scanA_kernel(int n) {
    __shared__ int sm[256];
    int t = threadIdx.x;
    int base = blockIdx.x * 1024 + t * 4;
    int s = 0;
#pragma unroll
    for (int i = 0; i < 4; i++) {
        int idx = base + i;
        if (idx < n) s += g_cnt[idx];
    }
    sm[t] = s;
    __syncthreads();
    for (int o = 128; o > 0; o >>= 1) {
        if (t < o) sm[t] += sm[t + o];
        __syncthreads();
    }
    if (t == 0) g_partial[blockIdx.x] = sm[0];
}
__global__ void scanB_kernel(int nb) {
    if (threadIdx.x == 0) {
        int run = 0;
        for (int i = 0; i < nb; i++) {
            int v = g_partial[i];
            g_partial[i] = run;
            run += v;
        }
    }
}
__global__ void scanC_kernel(int n) {
    __shared__ int sm[256];
    int t = threadIdx.x;
    int base = blockIdx.x * 1024 + t * 4;
    int v[4];
    int s = 0;
#pragma unroll
    for (int i = 0; i < 4; i++) {
        int idx = base + i;
        v[i] = (idx < n) ? g_cnt[idx] : 0;
        s += v[i];
    }
    sm[t] = s;
    __syncthreads();
#pragma unroll
    for (int o = 1; o < 256; o <<= 1) {
        int y = (t >= o) ? sm[t - o] : 0;
        __syncthreads();
        sm[t] += y;
        __syncthreads();
    }
    int off = g_partial[blockIdx.x] + sm[t] - s;  // exclusive
#pragma unroll
    for (int i = 0; i < 4; i++) {
        int idx = base + i;
        if (idx < n) {
            g_rowptr[idx] = off;
            g_cursor[idx] = off;
            off += v[i];
            if (idx == n - 1) g_rowptr[n] = off;
        }
    }
}

// ---------------- CSR fill with per-edge norm ----------------
__global__ void fill_kernel(const void* __restrict__ ei, int E) {
    int e = blockIdx.x * blockDim.x + threadIdx.x;
    if (e >= E) return;
    int is64 = g_is64;
    int s, d;
    load_edge(ei, e, E, is64, s, d);
    int p = atomicAdd(&g_cursor[d], 1);
    g_col[p] = s;
    g_val[p] = g_deg[s] * g_gate[e] * g_deg[d];  // g_deg == dinv now
}

// ---------------- GEMM: Y[n,128] = X[n,128] @ W[128,128] ----------------
__global__ __launch_bounds__(256) void gemm128_kernel(const float* __restrict__ X,
                                                      const float* __restrict__ W,
                                                      float* __restrict__ Y, int n) {
    int warp = (blockIdx.x * blockDim.x + threadIdx.x) >> 5;
    int lane = threadIdx.x & 31;
    int r0 = warp * 4;
    if (r0 >= n) return;
    const float4* W4 = (const float4*)W;
    float4 acc0 = {0, 0, 0, 0}, acc1 = acc0, acc2 = acc0, acc3 = acc0;
    if (r0 + 4 <= n) {
#pragma unroll 4
        for (int k = 0; k < 128; k++) {
            float4 w = W4[k * 32 + lane];
            float x0 = __ldg(&X[(size_t)(r0 + 0) * 128 + k]);
            float x1 = __ldg(&X[(size_t)(r0 + 1) * 128 + k]);
            float x2 = __ldg(&X[(size_t)(r0 + 2) * 128 + k]);
            float x3 = __ldg(&X[(size_t)(r0 + 3) * 128 + k]);
            acc0.x += x0 * w.x; acc0.y += x0 * w.y; acc0.z += x0 * w.z; acc0.w += x0 * w.w;
            acc1.x += x1 * w.x; acc1.y += x1 * w.y; acc1.z += x1 * w.z; acc1.w += x1 * w.w;
            acc2.x += x2 * w.x; acc2.y += x2 * w.y; acc2.z += x2 * w.z; acc2.w += x2 * w.w;
            acc3.x += x3 * w.x; acc3.y += x3 * w.y; acc3.z += x3 * w.z; acc3.w += x3 * w.w;
        }
        float4* Y4 = (float4*)Y;
        Y4[(size_t)(r0 + 0) * 32 + lane] = acc0;
        Y4[(size_t)(r0 + 1) * 32 + lane] = acc1;
        Y4[(size_t)(r0 + 2) * 32 + lane] = acc2;
        Y4[(size_t)(r0 + 3) * 32 + lane] = acc3;
    } else {
        for (int r = r0; r < n; r++) {
            float4 a = {0, 0, 0, 0};
            for (int k = 0; k < 128; k++) {
                float4 w = W4[k * 32 + lane];
                float xv = X[(size_t)r * 128 + k];
                a.x += xv * w.x; a.y += xv * w.y; a.z += xv * w.z; a.w += xv * w.w;
            }
            ((float4*)Y)[(size_t)r * 32 + lane] = a;
        }
    }
}

// ---------------- aggregate + bias + LN + relu + residual (warp per node) ----------------
__global__ __launch_bounds__(256) void agg_kernel(const float* __restrict__ xin,
                                                  const float* __restrict__ cb,
                                                  const float* __restrict__ lng,
                                                  const float* __restrict__ lnb,
                                                  float* __restrict__ xout, int n) {
    int v = (blockIdx.x * blockDim.x + threadIdx.x) >> 5;
    int lane = threadIdx.x & 31;
    if (v >= n) return;
    const float4* xw4 = (const float4*)g_xw;

    float dv = g_deg[v];  // dinv
    float4 t = xw4[(size_t)v * 32 + lane];
    float sl = dv * dv;
    float4 acc;
    acc.x = sl * t.x; acc.y = sl * t.y; acc.z = sl * t.z; acc.w = sl * t.w;

    int j = g_rowptr[v], end = g_rowptr[v + 1];
#pragma unroll 4
    for (; j < end; j++) {
        int s = __ldg(&g_col[j]);
        float w = __ldg(&g_val[j]);
        float4 m = xw4[(size_t)s * 32 + lane];
        acc.x += w * m.x; acc.y += w * m.y; acc.z += w * m.z; acc.w += w * m.w;
    }
    float4 b = ((const float4*)cb)[lane];
    acc.x += b.x; acc.y += b.y; acc.z += b.z; acc.w += b.w;

    // LayerNorm over 128
    float ssum = acc.x + acc.y + acc.z + acc.w;
#pragma unroll
    for (int o = 16; o > 0; o >>= 1) ssum += __shfl_xor_sync(0xffffffffu, ssum, o);
    float mean = ssum * (1.0f / 128.0f);
    float dx = acc.x - mean, dy = acc.y - mean, dz = acc.z - mean, dw = acc.w - mean;
    float vsum = dx * dx + dy * dy + dz * dz + dw * dw;
#pragma unroll
    for (int o = 16; o > 0; o >>= 1) vsum += __shfl_xor_sync(0xffffffffu, vsum, o);
    float rstd = rsqrtf(vsum * (1.0f / 128.0f) + 1e-5f);

    float4 g = ((const float4*)lng)[lane];
    float4 bb = ((const float4*)lnb)[lane];
    float4 xr = ((const float4*)xin)[(size_t)v * 32 + lane];
    float4 o4;
    o4.x = fmaxf(dx * rstd * g.x + bb.x, 0.0f) + xr.x;
    o4.y = fmaxf(dy * rstd * g.y + bb.y, 0.0f) + xr.y;
    o4.z = fmaxf(dz * rstd * g.z + bb.z, 0.0f) + xr.z;
    o4.w = fmaxf(dw * rstd * g.w + bb.w, 0.0f) + xr.w;
    ((float4*)xout)[(size_t)v * 32 + lane] = o4;
}

// ---------------- head: out[n,64] = X @ W[128,64] + b ----------------
__global__ __launch_bounds__(256) void head_kernel(const float* __restrict__ X,
                                                   const float* __restrict__ W,
                                                   const float* __restrict__ b,
                                                   float* __restrict__ out, int n) {
    int warp = (blockIdx.x * blockDim.x + threadIdx.x) >> 5;
    int lane = threadIdx.x & 31;
    int r0 = warp * 4;
    if (r0 >= n) return;
    const float2* W2 = (const float2*)W;
    float2 a0 = {0, 0}, a1 = {0, 0}, a2 = {0, 0}, a3 = {0, 0};
    int rows = n - r0;
    if (rows >= 4) {
#pragma unroll 4
        for (int k = 0; k < 128; k++) {
            float2 w = W2[k * 32 + lane];
            float x0 = __ldg(&X[(size_t)(r0 + 0) * 128 + k]);
            float x1 = __ldg(&X[(size_t)(r0 + 1) * 128 + k]);
            float x2 = __ldg(&X[(size_t)(r0 + 2) * 128 + k]);
            float x3 = __ldg(&X[(size_t)(r0 + 3) * 128 + k]);
            a0.x += x0 * w.x; a0.y += x0 * w.y;
            a1.x += x1 * w.x; a1.y += x1 * w.y;
            a2.x += x2 * w.x; a2.y += x2 * w.y;
            a3.x += x3 * w.x; a3.y += x3 * w.y;
        }
        float2 bb = ((const float2*)b)[lane];
        float2* o2 = (float2*)out;
        a0.x += bb.x; a0.y += bb.y; a1.x += bb.x; a1.y += bb.y;
        a2.x += bb.x; a2.y += bb.y; a3.x += bb.x; a3.y += bb.y;
        o2[(size_t)(r0 + 0) * 32 + lane] = a0;
        o2[(size_t)(r0 + 1) * 32 + lane] = a1;
        o2[(size_t)(r0 + 2) * 32 + lane] = a2;
        o2[(size_t)(r0 + 3) * 32 + lane] = a3;
    } else {
        for (int r = r0; r < n; r++) {
            float2 a = {0, 0};
            for (int k = 0; k < 128; k++) {
                float2 w = W2[k * 32 + lane];
                float xv = X[(size_t)r * 128 + k];
                a.x += xv * w.x; a.y += xv * w.y;
            }
            float2 bb = ((const float2*)b)[lane];
            a.x += bb.x; a.y += bb.y;
            ((float2*)out)[(size_t)r * 32 + lane] = a;
        }
    }
}

// ---------------- launch ----------------
extern "C" void kernel_launch(void* const* d_in, const int* in_sizes, int n_in,
                              void* d_out, int out_size) {
    const float* x     = (const float*)d_in[0];
    const float* motif = (const float*)d_in[1];
    const void*  ei    = d_in[2];
    const float* gw1   = (const float*)d_in[3];
    const float* gb1   = (const float*)d_in[4];
    const float* gw2   = (const float*)d_in[5];
    const float* gb2   = (const float*)d_in[6];
    const float* cw    = (const float*)d_in[7];
    const float* cb    = (const float*)d_in[8];
    const float* lng   = (const float*)d_in[9];
    const float* lnb   = (const float*)d_in[10];
    const float* hw    = (const float*)d_in[11];
    const float* hb    = (const float*)d_in[12];

    int n = in_sizes[0] / IND;
    int E = in_sizes[2] / 2;

    detect_kernel<<<1, 32>>>((const int*)ei);
    init_kernel<<<(n + 255) / 256, 256>>>(n);
    gate_kernel<<<(E + 255) / 256, 256>>>(ei, motif, gw1, gb1, gw2, gb2, E);
    dinv_kernel<<<(n + 255) / 256, 256>>>(n);

    int nb = (n + 1023) / 1024;
    scanA_kernel<<<nb, 256>>>(n);
    scanB_kernel<<<1, 32>>>(nb);
    scanC_kernel<<<nb, 256>>>(n);
    fill_kernel<<<(E + 255) / 256, 256>>>(ei, E);

    float* xw   = nullptr;
    float* xbuf = nullptr;
    cudaGetSymbolAddress((void**)&xw, g_xw);
    cudaGetSymbolAddress((void**)&xbuf, g_xbuf);

    int gemm_blocks = (((n + 3) / 4) * 32 + 255) / 256;
    int agg_blocks  = (n * 32 + 255) / 256;

    // layer 0
    gemm128_kernel<<<gemm_blocks, 256>>>(x, cw, xw, n);
    agg_kernel<<<agg_blocks, 256>>>(x, cb, lng, lnb, xbuf, n);
    // layer 1
    gemm128_kernel<<<gemm_blocks, 256>>>(xbuf, cw + IND * IND, xw, n);
    agg_kernel<<<agg_blocks, 256>>>(xbuf, cb + IND, lng + IND, lnb + IND, xbuf, n);
    // head
    head_kernel<<<gemm_blocks, 256>>>(xbuf, hw, hb, (float*)d_out, n);
}

// round 2
// speedup vs baseline: 1.0458x; 1.0458x over previous
#include <cuda_runtime.h>

#define NN   100000
#define EE   1600000
#define IND  128
#define OUTD 64
#define MDIM 16
#define GHD  64

// ---------------- static device scratch (no allocations allowed) ----------------
__device__ float g_gate[EE];
__device__ float g_deg[NN];                 // deg, then dinv in-place
__device__ int   g_cnt[NN];
__device__ int   g_rowptr[NN + 1];
__device__ int   g_cursor[NN];
__device__ unsigned long long g_cv[EE];     // packed (val<<32 | col)
__device__ float g_xw[(size_t)NN * IND];    // 51.2 MB (L2-resident working set)
__device__ float g_xbuf[(size_t)NN * IND];  // node features between layers
__device__ int   g_partial[1024];
__device__ int   g_is64;

// ---------------- helpers ----------------
__device__ __forceinline__ void load_edge(const void* ei, int e, int E, int is64,
                                          int& s, int& d) {
    if (is64) {
        const long long* p = (const long long*)ei;
        s = (int)p[e];
        d = (int)p[E + e];
    } else {
        const int* p = (const int*)ei;
        s = p[e];
        d = p[E + e];
    }
}

__device__ __forceinline__ unsigned long long pack2(float lo, float hi) {
    unsigned long long r;
    asm("mov.b64 %0, {%1, %2};" : "=l"(r) : "r"(__float_as_uint(lo)), "r"(__float_as_uint(hi)));
    return r;
}
__device__ __forceinline__ void unpack2(unsigned long long v, float& lo, float& hi) {
    unsigned int a, b;
    asm("mov.b64 {%0, %1}, %2;" : "=r"(a), "=r"(b) : "l"(v));
    lo = __uint_as_float(a);
    hi = __uint_as_float(b);
}
__device__ __forceinline__ void fma2(unsigned long long& acc, unsigned long long a,
                                     unsigned long long b) {
    asm("fma.rn.f32x2 %0, %1, %2, %0;" : "+l"(acc) : "l"(a), "l"(b));
}

union F4U {
    float4 f;
    ulonglong2 u;
    float s[4];
};

// ---------------- nop (profiling alignment) ----------------
__global__ void nop_kernel() {}

// ---------------- fused init + dtype detection ----------------
__global__ void initdetect_kernel(const int* ei, int n) {
    int i = blockIdx.x * blockDim.x + threadIdx.x;
    if (i < n) {
        g_deg[i] = 1.0f;  // self-loop weight
        g_cnt[i] = 0;
    }
    if (blockIdx.x == 0 && threadIdx.x == 0) {
        int all0 = 1;
        for (int k = 1; k < 256; k += 2)
            if (ei[k] != 0) { all0 = 0; break; }
        g_is64 = all0;  // int64: odd words are high halves of values < 2^17 -> 0
    }
}

// ---------------- edge gate MLP (f32x2 + LDS.128) + degree + histogram ----------------
__global__ __launch_bounds__(256) void gate_kernel(
    const void* __restrict__ ei, const float* __restrict__ motif,
    const float* __restrict__ w1, const float* __restrict__ b1,
    const float* __restrict__ w2, const float* __restrict__ b2, int E) {
    __shared__ __align__(16) float sW1[GHD * GHD];  // [k][j], 16 KB
    __shared__ float sw2[GHD];
    __shared__ float sb1[GHD];
    for (int i = threadIdx.x; i < GHD * GHD; i += blockDim.x) sW1[i] = w1[i];
    if (threadIdx.x < GHD) {
        sw2[threadIdx.x] = w2[threadIdx.x];
        sb1[threadIdx.x] = b1[threadIdx.x];
    }
    __syncthreads();

    int e = blockIdx.x * blockDim.x + threadIdx.x;
    if (e >= E) return;
    int is64 = g_is64;
    int s, d;
    load_edge(ei, e, E, is64, s, d);

    float mu[MDIM], mv[MDIM];
    const float4* m4 = (const float4*)motif;
#pragma unroll
    for (int i = 0; i < 4; i++) {
        float4 a = m4[s * 4 + i];
        mu[i * 4 + 0] = a.x; mu[i * 4 + 1] = a.y; mu[i * 4 + 2] = a.z; mu[i * 4 + 3] = a.w;
        float4 b = m4[d * 4 + i];
        mv[i * 4 + 0] = b.x; mv[i * 4 + 1] = b.y; mv[i * 4 + 2] = b.z; mv[i * 4 + 3] = b.w;
    }

    // acc[q].x covers hidden units 4q,4q+1; acc[q].y covers 4q+2,4q+3
    ulonglong2 acc[GHD / 4];
#pragma unroll
    for (int q = 0; q < GHD / 4; q++) {
        acc[q].x = pack2(sb1[4 * q + 0], sb1[4 * q + 1]);
        acc[q].y = pack2(sb1[4 * q + 2], sb1[4 * q + 3]);
    }

    const ulonglong2* Wq = (const ulonglong2*)sW1;  // row k = 16 ulonglong2
    auto body = [&](int k, float f) {
        unsigned long long ff = pack2(f, f);
#pragma unroll
        for (int q = 0; q < GHD / 4; q++) {
            ulonglong2 w = Wq[k * (GHD / 4) + q];  // LDS.128 broadcast
            fma2(acc[q].x, ff, w.x);
            fma2(acc[q].y, ff, w.y);
        }
    };
#pragma unroll
    for (int k = 0; k < 16; k++) body(k, mu[k]);
#pragma unroll
    for (int k = 0; k < 16; k++) body(16 + k, mv[k]);
#pragma unroll
    for (int k = 0; k < 16; k++) body(32 + k, fabsf(mu[k] - mv[k]));
#pragma unroll
    for (int k = 0; k < 16; k++) body(48 + k, mu[k] * mv[k]);

    float g = b2[0];
#pragma unroll
    for (int q = 0; q < GHD / 4; q++) {
        float a0, a1, a2, a3;
        unpack2(acc[q].x, a0, a1);
        unpack2(acc[q].y, a2, a3);
        g += fmaxf(a0, 0.0f) * sw2[4 * q + 0] + fmaxf(a1, 0.0f) * sw2[4 * q + 1] +
             fmaxf(a2, 0.0f) * sw2[4 * q + 2] + fmaxf(a3, 0.0f) * sw2[4 * q + 3];
    }
    float gate = 1.0f / (1.0f + __expf(-g));
    g_gate[e] = gate;
    atomicAdd(&g_deg[d], gate);
    atomicAdd(&g_cnt[d], 1);
}

// ---------------- fused dinv + scanA ----------------
__global__ void dinv_scanA_kernel(int n, int nb) {
    if ((int)blockIdx.x >= nb) {
        int i = (blockIdx.x - nb) * blockDim.x + threadIdx.x;
        if (i < n) g_deg[i] = rsqrtf(g_deg[i]);  // deg >= 1 always
        return;
    }
    __shared__ int sm[256];
    int t = threadIdx.x;
    int base = blockIdx.x * 1024 + t * 4;
    int s = 0;
#pragma unroll
    for (int i = 0; i < 4; i++) {
        int idx = base + i;
        if (idx < n) s += g_cnt[idx];
    }
    sm[t] = s;
    __syncthreads();
    for (int o = 128; o > 0; o >>= 1) {
        if (t < o) sm[t] += sm[t + o];
        __syncthreads();
    }
    if (t == 0) g_partial[blockIdx.x] = sm[0];
}

__global__ void scanB_kernel(int nb) {
    if (threadIdx.x == 0) {
        int run = 0;
        for (int i = 0; i < nb; i++) {
            int v = g_partial[i];
            g_partial[i] = run;
            run += v;
        }
    }
}

__global__ void scanC_kernel(int n) {
    __shared__ int sm[256];
    int t = threadIdx.x;
    int base = blockIdx.x * 1024 + t * 4;
    int v[4];
    int s = 0;
#pragma unroll
    for (int i = 0; i < 4; i++) {
        int idx = base + i;
        v[i] = (idx < n) ? g_cnt[idx] : 0;
        s += v[i];
    }
    sm[t] = s;
    __syncthreads();
#pragma unroll
    for (int o = 1; o < 256; o <<= 1) {
        int y = (t >= o) ? sm[t - o] : 0;
        __syncthreads();
        sm[t] += y;
        __syncthreads();
    }
    int off = g_partial[blockIdx.x] + sm[t] - s;  // exclusive
#pragma unroll
    for (int i = 0; i < 4; i++) {
        int idx = base + i;
        if (idx < n) {
            g_rowptr[idx] = off;
            g_cursor[idx] = off;
            off += v[i];
            if (idx == n - 1) g_rowptr[n] = off;
        }
    }
}

// ---------------- CSR fill with per-edge norm (packed col+val) ----------------
__global__ void fill_kernel(const void* __restrict__ ei, int E) {
    int e = blockIdx.x * blockDim.x + threadIdx.x;
    if (e >= E) return;
    int is64 = g_is64;
    int s, d;
    load_edge(ei, e, E, is64, s, d);
    int p = atomicAdd(&g_cursor[d], 1);
    float val = g_deg[s] * g_gate[e] * g_deg[d];  // g_deg == dinv now
    g_cv[p] = ((unsigned long long)__float_as_uint(val) << 32) | (unsigned int)s;
}

// ---------------- GEMM: Y[n,128] = X[n,128] @ W[128,128], f32x2 ----------------
__global__ __launch_bounds__(256) void gemm128_kernel(const float* __restrict__ X,
                                                      const float* __restrict__ W,
                                                      float* __restrict__ Y, int n) {
    int warp = (blockIdx.x * blockDim.x + threadIdx.x) >> 5;
    int lane = threadIdx.x & 31;
    int r0 = warp * 4;
    if (r0 >= n) return;
    const ulonglong2* W2 = (const ulonglong2*)W;  // row k: 32 ulonglong2
    const float4* X4 = (const float4*)X;
    if (r0 + 4 <= n) {
        ulonglong2 a0, a1, a2, a3;
        a0.x = a0.y = a1.x = a1.y = a2.x = a2.y = a3.x = a3.y = 0ULL;
        for (int k4 = 0; k4 < 32; k4++) {
            F4U x0, x1, x2, x3;
            x0.f = __ldg(&X4[(size_t)(r0 + 0) * 32 + k4]);
            x1.f = __ldg(&X4[(size_t)(r0 + 1) * 32 + k4]);
            x2.f = __ldg(&X4[(size_t)(r0 + 2) * 32 + k4]);
            x3.f = __ldg(&X4[(size_t)(r0 + 3) * 32 + k4]);
#pragma unroll
            for (int kk = 0; kk < 4; kk++) {
                ulonglong2 w = __ldg(&W2[(size_t)(k4 * 4 + kk) * 32 + lane]);
                unsigned long long f0 = pack2(x0.s[kk], x0.s[kk]);
                unsigned long long f1 = pack2(x1.s[kk], x1.s[kk]);
                unsigned long long f2 = pack2(x2.s[kk], x2.s[kk]);
                unsigned long long f3 = pack2(x3.s[kk], x3.s[kk]);
                fma2(a0.x, f0, w.x); fma2(a0.y, f0, w.y);
                fma2(a1.x, f1, w.x); fma2(a1.y, f1, w.y);
                fma2(a2.x, f2, w.x); fma2(a2.y, f2, w.y);
                fma2(a3.x, f3, w.x); fma2(a3.y, f3, w.y);
            }
        }
        F4U o0, o1, o2, o3;
        o0.u = a0; o1.u = a1; o2.u = a2; o3.u = a3;
        float4* Y4 = (float4*)Y;
        Y4[(size_t)(r0 + 0) * 32 + lane] = o0.f;
        Y4[(size_t)(r0 + 1) * 32 + lane] = o1.f;
        Y4[(size_t)(r0 + 2) * 32 + lane] = o2.f;
        Y4[(size_t)(r0 + 3) * 32 + lane] = o3.f;
    } else {
        const float4* W4 = (const float4*)W;
        for (int r = r0; r < n; r++) {
            float4 a = {0, 0, 0, 0};
            for (int k = 0; k < 128; k++) {
                float4 w = W4[k * 32 + lane];
                float xv = X[(size_t)r * 128 + k];
                a.x += xv * w.x; a.y += xv * w.y; a.z += xv * w.z; a.w += xv * w.w;
            }
            ((float4*)Y)[(size_t)r * 32 + lane] = a;
        }
    }
}

// ---------------- aggregate + bias + LN + relu + residual (warp per node) ----------------
__global__ __launch_bounds__(256) void agg_kernel(const float* __restrict__ xin,
                                                  const float* __restrict__ cb,
                                                  const float* __restrict__ lng,
                                                  const float* __restrict__ lnb,
                                                  float* __restrict__ xout, int n) {
    int v = (blockIdx.x * blockDim.x + threadIdx.x) >> 5;
    int lane = threadIdx.x & 31;
    if (v >= n) return;
    const float4* xw4 = (const float4*)g_xw;

    float dv = g_deg[v];  // dinv
    F4U t;
    t.f = xw4[(size_t)v * 32 + lane];
    float sl = dv * dv;
    unsigned long long slp = pack2(sl, sl);
    ulonglong2 acc;
    acc.x = 0ULL; acc.y = 0ULL;
    fma2(acc.x, slp, t.u.x);
    fma2(acc.y, slp, t.u.y);

    int j = g_rowptr[v], end = g_rowptr[v + 1];
#pragma unroll 4
    for (; j < end; j++) {
        unsigned long long cv = __ldg(&g_cv[j]);
        int s = (int)(unsigned int)cv;
        float w = __uint_as_float((unsigned int)(cv >> 32));
        F4U m;
        m.f = xw4[(size_t)s * 32 + lane];
        unsigned long long wp = pack2(w, w);
        fma2(acc.x, wp, m.u.x);
        fma2(acc.y, wp, m.u.y);
    }
    float ax, ay, az, aw;
    unpack2(acc.x, ax, ay);
    unpack2(acc.y, az, aw);
    float4 b = ((const float4*)cb)[lane];
    ax += b.x; ay += b.y; az += b.z; aw += b.w;

    // LayerNorm over 128
    float ssum = ax + ay + az + aw;
#pragma unroll
    for (int o = 16; o > 0; o >>= 1) ssum += __shfl_xor_sync(0xffffffffu, ssum, o);
    float mean = ssum * (1.0f / 128.0f);
    float dx = ax - mean, dy = ay - mean, dz = az - mean, dw = aw - mean;
    float vsum = dx * dx + dy * dy + dz * dz + dw * dw;
#pragma unroll
    for (int o = 16; o > 0; o >>= 1) vsum += __shfl_xor_sync(0xffffffffu, vsum, o);
    float rstd = rsqrtf(vsum * (1.0f / 128.0f) + 1e-5f);

    float4 g = ((const float4*)lng)[lane];
    float4 bb = ((const float4*)lnb)[lane];
    float4 xr = ((const float4*)xin)[(size_t)v * 32 + lane];
    float4 o4;
    o4.x = fmaxf(dx * rstd * g.x + bb.x, 0.0f) + xr.x;
    o4.y = fmaxf(dy * rstd * g.y + bb.y, 0.0f) + xr.y;
    o4.z = fmaxf(dz * rstd * g.z + bb.z, 0.0f) + xr.z;
    o4.w = fmaxf(dw * rstd * g.w + bb.w, 0.0f) + xr.w;
    ((float4*)xout)[(size_t)v * 32 + lane] = o4;
}

// ---------------- head: out[n,64] = X @ W[128,64] + b, 8 rows/warp f32x2 ----------------
__global__ __launch_bounds__(256) void head_kernel(const float* __restrict__ X,
                                                   const float* __restrict__ W,
                                                   const float* __restrict__ b,
                                                   float* __restrict__ out, int n) {
    int warp = (blockIdx.x * blockDim.x + threadIdx.x) >> 5;
    int lane = threadIdx.x & 31;
    int r0 = warp * 8;
    if (r0 >= n) return;
    const unsigned long long* Wp = (const unsigned long long*)W;  // row k: 32 ull
    const float4* X4 = (const float4*)X;
    if (r0 + 8 <= n) {
        unsigned long long a[8];
#pragma unroll
        for (int r = 0; r < 8; r++) a[r] = 0ULL;
        for (int k4 = 0; k4 < 32; k4++) {
            F4U xr[8];
#pragma unroll
            for (int r = 0; r < 8; r++)
                xr[r].f = __ldg(&X4[(size_t)(r0 + r) * 32 + k4]);
#pragma unroll
            for (int kk = 0; kk < 4; kk++) {
                unsigned long long w = __ldg(&Wp[(size_t)(k4 * 4 + kk) * 32 + lane]);
#pragma unroll
                for (int r = 0; r < 8; r++) {
                    unsigned long long f = pack2(xr[r].s[kk], xr[r].s[kk]);
                    fma2(a[r], f, w);
                }
            }
        }
        float2 bb = ((const float2*)b)[lane];
        float2* o2 = (float2*)out;
#pragma unroll
        for (int r = 0; r < 8; r++) {
            float lo, hi;
            unpack2(a[r], lo, hi);
            float2 o;
            o.x = lo + bb.x;
            o.y = hi + bb.y;
            o2[(size_t)(r0 + r) * 32 + lane] = o;
        }
    } else {
        const float2* W2 = (const float2*)W;
        for (int r = r0; r < n; r++) {
            float2 a = {0, 0};
            for (int k = 0; k < 128; k++) {
                float2 w = W2[k * 32 + lane];
                float xv = X[(size_t)r * 128 + k];
                a.x += xv * w.x; a.y += xv * w.y;
            }
            float2 bb = ((const float2*)b)[lane];
            a.x += bb.x; a.y += bb.y;
            ((float2*)out)[(size_t)r * 32 + lane] = a;
        }
    }
}

// ---------------- launch ----------------
extern "C" void kernel_launch(void* const* d_in, const int* in_sizes, int n_in,
                              void* d_out, int out_size) {
    const float* x     = (const float*)d_in[0];
    const float* motif = (const float*)d_in[1];
    const void*  ei    = d_in[2];
    const float* gw1   = (const float*)d_in[3];
    const float* gb1   = (const float*)d_in[4];
    const float* gw2   = (const float*)d_in[5];
    const float* gb2   = (const float*)d_in[6];
    const float* cw    = (const float*)d_in[7];
    const float* cb    = (const float*)d_in[8];
    const float* lng   = (const float*)d_in[9];
    const float* lnb   = (const float*)d_in[10];
    const float* hw    = (const float*)d_in[11];
    const float* hb    = (const float*)d_in[12];

    int n = in_sizes[0] / IND;
    int E = in_sizes[2] / 2;

    // launch index 0
    initdetect_kernel<<<(n + 255) / 256, 256>>>((const int*)ei, n);
    // indices 1,2: nops so gate lands at index 3 (the slot ncu captured in R1)
    nop_kernel<<<1, 32>>>();
    nop_kernel<<<1, 32>>>();
    // index 3
    gate_kernel<<<(E + 255) / 256, 256>>>(ei, motif, gw1, gb1, gw2, gb2, E);

    int nb = (n + 1023) / 1024;
    dinv_scanA_kernel<<<nb + (n + 255) / 256, 256>>>(n, nb);
    scanB_kernel<<<1, 32>>>(nb);
    scanC_kernel<<<nb, 256>>>(n);
    fill_kernel<<<(E + 255) / 256, 256>>>(ei, E);

    float* xw   = nullptr;
    float* xbuf = nullptr;
    cudaGetSymbolAddress((void**)&xw, g_xw);
    cudaGetSymbolAddress((void**)&xbuf, g_xbuf);

    int gemm_blocks = (((n + 3) / 4) * 32 + 255) / 256;
    int agg_blocks  = (n * 32 + 255) / 256;
    int head_blocks = (((n + 7) / 8) * 32 + 255) / 256;

    // layer 0
    gemm128_kernel<<<gemm_blocks, 256>>>(x, cw, xw, n);
    agg_kernel<<<agg_blocks, 256>>>(x, cb, lng, lnb, xbuf, n);
    // layer 1
    gemm128_kernel<<<gemm_blocks, 256>>>(xbuf, cw + IND * IND, xw, n);
    agg_kernel<<<agg_blocks, 256>>>(xbuf, cb + IND, lng + IND, lnb + IND, xbuf, n);
    // head
    head_kernel<<<head_blocks, 256>>>(xbuf, hw, hb, (float*)d_out, n);
}